// round 1
// baseline (speedup 1.0000x reference)
#include <cuda_runtime.h>
#include <cuda_bf16.h>
#include <cstddef>

// Problem constants
#define BATCH   2
#define TLEN    2048       // Tq == Tv
#define DMODEL  512
#define NHEADS  8
#define DHEAD   64

// Tiling
#define TQ      32         // queries per block
#define TK      64         // keys per tile
#define KSPLIT  8          // k-range splits per (b, q-tile)
#define KRANGE  (TLEN / KSPLIT)   // 256 keys per block

// Shared layout (floats): Ksh[TK*DMODEL] | Vsh[TK*DHEAD] | Psh[NHEADS*TK*TQ]
#define KSH_FLOATS  (TK * DMODEL)                 // 32768
#define VSH_FLOATS  (TK * DHEAD)                  // 4096
#define PSH_FLOATS  (NHEADS * TK * TQ)            // 16384
#define SMEM_FLOATS (KSH_FLOATS + VSH_FLOATS + PSH_FLOATS)
#define SMEM_BYTES  (SMEM_FLOATS * 4)             // 212992

// Scratch: projected (and pre-scaled) K matrix, [B][T][DMODEL]
__device__ float g_K[BATCH * TLEN * DMODEL];

// ---------------------------------------------------------------------------
// Zero the output (it is poisoned before timing; atomics need zeros).
// grid 2048 x 256 threads x float4 = 2,097,152 floats
// ---------------------------------------------------------------------------
__global__ void zero_kernel(float4* __restrict__ out) {
    out[(size_t)blockIdx.x * blockDim.x + threadIdx.x] = make_float4(0.f, 0.f, 0.f, 0.f);
}

// ---------------------------------------------------------------------------
// Conv1d(kernel=1) == pointwise linear: gK[b,t,o] = 0.125*(bias[o] + sum_c v[b,t,c]*W[o,c])
// (0.125 = dh^-0.5 folded in). Grid: (TLEN/16, BATCH), 256 threads.
// ---------------------------------------------------------------------------
__global__ void conv_kernel(const float* __restrict__ value,
                            const float* __restrict__ w,
                            const float* __restrict__ bias) {
    __shared__ float vsh[16 * DHEAD];
    const int b   = blockIdx.y;
    const int t0  = blockIdx.x * 16;
    const int tid = threadIdx.x;

    // load 16 value rows (1024 floats) coalesced
    const float4* vg = (const float4*)(value + ((size_t)(b * TLEN + t0)) * DHEAD);
    ((float4*)vsh)[tid] = vg[tid];
    __syncthreads();

    for (int o = tid; o < DMODEL; o += 256) {
        float wreg[DHEAD];
        const float4* wp = (const float4*)(w + (size_t)o * DHEAD);
#pragma unroll
        for (int j = 0; j < 16; j++) {
            float4 ww = wp[j];
            wreg[4 * j + 0] = ww.x; wreg[4 * j + 1] = ww.y;
            wreg[4 * j + 2] = ww.z; wreg[4 * j + 3] = ww.w;
        }
        const float bb = bias[o];
        for (int t = 0; t < 16; t++) {
            float s = bb;
#pragma unroll
            for (int c = 0; c < DHEAD; c++) s += wreg[c] * vsh[t * DHEAD + c];
            g_K[((size_t)(b * TLEN + t0 + t)) * DMODEL + o] = s * 0.125f;
        }
    }
}

// ---------------------------------------------------------------------------
// Attention with softmax over HEADS (pointwise in (q,k)):
//   out[b,q,h*64+d] += sum_{k in range} softmax_h(q_h . K_h(k))[h] * value[b,k,d]
// Block: 256 threads, warp w == head h, lane == qi. TQ=32 queries, loops over
// KRANGE keys in TK=64 tiles. Grid: (TLEN/TQ, KSPLIT, BATCH).
// ---------------------------------------------------------------------------
extern __shared__ float smem[];

__global__ void __launch_bounds__(256, 1)
attn_kernel(const float* __restrict__ query,
            const float* __restrict__ value,
            float* __restrict__ out) {
    float* Ksh = smem;
    float* Vsh = smem + KSH_FLOATS;
    float* Psh = smem + KSH_FLOATS + VSH_FLOATS;

    const int tid = threadIdx.x;
    const int h   = tid >> 5;   // warp index == head
    const int qi  = tid & 31;   // lane == query within tile
    const int q0  = blockIdx.x * TQ;
    const int k0  = blockIdx.y * KRANGE;
    const int b   = blockIdx.z;

    // q row for (h, qi) into registers (reused across all k tiles)
    float qreg[DHEAD];
    {
        const float4* qp = (const float4*)(query + ((size_t)(b * TLEN + q0 + qi)) * DMODEL + h * DHEAD);
#pragma unroll
        for (int j = 0; j < 16; j++) {
            float4 t = qp[j];
            qreg[4 * j + 0] = t.x; qreg[4 * j + 1] = t.y;
            qreg[4 * j + 2] = t.z; qreg[4 * j + 3] = t.w;
        }
    }

    float oacc[DHEAD];
#pragma unroll
    for (int d = 0; d < DHEAD; d++) oacc[d] = 0.f;

    for (int kt = 0; kt < KRANGE; kt += TK) {
        __syncthreads();  // previous tile's phase C done before overwriting tiles

        // ---- load K tile (TK x DMODEL) and V tile (TK x DHEAD), coalesced ----
        {
            const float4* gk4 = (const float4*)(g_K + ((size_t)(b * TLEN + k0 + kt)) * DMODEL);
            float4* k4 = (float4*)Ksh;
            for (int i = tid; i < KSH_FLOATS / 4; i += 256) k4[i] = gk4[i];
            const float4* gv4 = (const float4*)(value + ((size_t)(b * TLEN + k0 + kt)) * DHEAD);
            float4* v4 = (float4*)Vsh;
            for (int i = tid; i < VSH_FLOATS / 4; i += 256) v4[i] = gv4[i];
        }
        __syncthreads();

        // ---- Phase A: logits S[h][ki][qi] = qreg . Ksh[ki][h*64:...] ----
#pragma unroll 2
        for (int ki = 0; ki < TK; ki++) {
            const float4* kp = (const float4*)(Ksh + ki * DMODEL + h * DHEAD);  // warp broadcast
            float s0 = 0.f, s1 = 0.f, s2 = 0.f, s3 = 0.f;
#pragma unroll
            for (int j = 0; j < 16; j++) {
                float4 kk = kp[j];
                s0 += qreg[4 * j + 0] * kk.x;
                s1 += qreg[4 * j + 1] * kk.y;
                s2 += qreg[4 * j + 2] * kk.z;
                s3 += qreg[4 * j + 3] * kk.w;
            }
            Psh[h * (TK * TQ) + ki * TQ + qi] = (s0 + s1) + (s2 + s3);
        }
        __syncthreads();

        // ---- Phase B: softmax over the 8 heads for each (ki, qi) pair ----
#pragma unroll
        for (int r = 0; r < (TQ * TK) / 256; r++) {
            const int pi  = r * 256 + tid;
            const int kki = pi >> 5;       // ki
            const int qqi = pi & 31;       // qi (lane-consecutive -> conflict-free)
            float l[NHEADS];
#pragma unroll
            for (int hh = 0; hh < NHEADS; hh++)
                l[hh] = Psh[hh * (TK * TQ) + kki * TQ + qqi];
            float m = l[0];
#pragma unroll
            for (int hh = 1; hh < NHEADS; hh++) m = fmaxf(m, l[hh]);
            float ssum = 0.f;
#pragma unroll
            for (int hh = 0; hh < NHEADS; hh++) { l[hh] = __expf(l[hh] - m); ssum += l[hh]; }
            const float inv = __fdividef(1.f, ssum);
#pragma unroll
            for (int hh = 0; hh < NHEADS; hh++)
                Psh[hh * (TK * TQ) + kki * TQ + qqi] = l[hh] * inv;
        }
        __syncthreads();

        // ---- Phase C: oacc[d] += P[h][ki][qi] * Vsh[ki][d] ----
        for (int ki = 0; ki < TK; ki++) {
            const float p = Psh[h * (TK * TQ) + ki * TQ + qi];
            const float4* vp = (const float4*)(Vsh + ki * DHEAD);  // warp broadcast
#pragma unroll
            for (int j = 0; j < 16; j++) {
                float4 vv = vp[j];
                oacc[4 * j + 0] += p * vv.x;
                oacc[4 * j + 1] += p * vv.y;
                oacc[4 * j + 2] += p * vv.z;
                oacc[4 * j + 3] += p * vv.w;
            }
        }
    }

    // ---- combine partial results over k-splits ----
    float* op = out + ((size_t)(b * TLEN + q0 + qi)) * DMODEL + h * DHEAD;
#pragma unroll
    for (int d = 0; d < DHEAD; d++) atomicAdd(op + d, oacc[d]);
}

// ---------------------------------------------------------------------------
extern "C" void kernel_launch(void* const* d_in, const int* in_sizes, int n_in,
                              void* d_out, int out_size) {
    const float* query = (const float*)d_in[0];   // [2,2048,512]
    const float* value = (const float*)d_in[1];   // [2,2048,64]
    const float* convw = (const float*)d_in[2];   // [512,64,1]
    const float* convb = (const float*)d_in[3];   // [512]
    float* out = (float*)d_out;                   // [2,2048,512]

    cudaFuncSetAttribute(attn_kernel, cudaFuncAttributeMaxDynamicSharedMemorySize, SMEM_BYTES);

    zero_kernel<<<2048, 256>>>((float4*)out);
    conv_kernel<<<dim3(TLEN / 16, BATCH), 256>>>(value, convw, convb);
    attn_kernel<<<dim3(TLEN / TQ, KSPLIT, BATCH), 256, SMEM_BYTES>>>(query, value, out);
}

// round 3
// speedup vs baseline: 1.1406x; 1.1406x over previous
#include <cuda_runtime.h>
#include <cuda_bf16.h>
#include <cstddef>

// Problem constants
#define BATCH   2
#define TLEN    2048       // Tq == Tv
#define DMODEL  512
#define NHEADS  8
#define DHEAD   64

// Tiling
#define TQ      32         // queries per block
#define TK      64         // keys per tile
#define KSPLIT  8          // k-range splits per (b, q-tile)
#define KRANGE  (TLEN / KSPLIT)   // 256 keys per block

// Shared layout (floats): Ksh[TK*DMODEL] | Vsh[TK*DHEAD] | Psh[NHEADS*TK*TQ]
#define KSH_FLOATS  (TK * DMODEL)                 // 32768
#define VSH_FLOATS  (TK * DHEAD)                  // 4096
#define PSH_FLOATS  (NHEADS * TK * TQ)            // 16384
#define SMEM_FLOATS (KSH_FLOATS + VSH_FLOATS + PSH_FLOATS)
#define SMEM_BYTES  (SMEM_FLOATS * 4)             // 212992

#define OUT_FLOATS  (BATCH * TLEN * DMODEL)       // 2,097,152

// Scratch: projected (pre-scaled) K matrix and per-split partial outputs
__device__ float g_K[BATCH * TLEN * DMODEL];
__device__ float g_part[KSPLIT * OUT_FLOATS];     // 64 MB

// ---------------------------------------------------------------------------
// Packed f32x2 helpers (FFMA2 — ptxas will not auto-fuse; PTX only)
// ---------------------------------------------------------------------------
typedef unsigned long long ull;

__device__ __forceinline__ ull pk2(float lo, float hi) {
    ull r; asm("mov.b64 %0, {%1, %2};" : "=l"(r) : "f"(lo), "f"(hi)); return r;
}
__device__ __forceinline__ void upk2(ull v, float& lo, float& hi) {
    asm("mov.b64 {%0, %1}, %2;" : "=f"(lo), "=f"(hi) : "l"(v));
}
__device__ __forceinline__ ull ffma2(ull a, ull b, ull c) {
    ull d; asm("fma.rn.f32x2 %0, %1, %2, %3;" : "=l"(d) : "l"(a), "l"(b), "l"(c)); return d;
}

// ---------------------------------------------------------------------------
// Conv1d(kernel=1) == pointwise linear: gK[b,t,o] = 0.125*(bias[o] + sum_c v[b,t,c]*W[o,c])
// ---------------------------------------------------------------------------
__global__ void conv_kernel(const float* __restrict__ value,
                            const float* __restrict__ w,
                            const float* __restrict__ bias) {
    __shared__ float vsh[16 * DHEAD];
    const int b   = blockIdx.y;
    const int t0  = blockIdx.x * 16;
    const int tid = threadIdx.x;

    const float4* vg = (const float4*)(value + ((size_t)(b * TLEN + t0)) * DHEAD);
    ((float4*)vsh)[tid] = vg[tid];
    __syncthreads();

    for (int o = tid; o < DMODEL; o += 256) {
        ull wreg2[32];
        const float4* wp = (const float4*)(w + (size_t)o * DHEAD);
#pragma unroll
        for (int j = 0; j < 16; j++) {
            float4 ww = wp[j];
            wreg2[2 * j + 0] = pk2(ww.x, ww.y);
            wreg2[2 * j + 1] = pk2(ww.z, ww.w);
        }
        const float bb = bias[o];
        for (int t = 0; t < 16; t++) {
            ull a0 = 0ull, a1 = 0ull;
            const ull* v2 = (const ull*)(vsh + t * DHEAD);
#pragma unroll
            for (int c = 0; c < 32; c += 2) {
                a0 = ffma2(wreg2[c],     v2[c],     a0);
                a1 = ffma2(wreg2[c + 1], v2[c + 1], a1);
            }
            float x0, x1, y0, y1;
            upk2(a0, x0, x1); upk2(a1, y0, y1);
            const float s = bb + ((x0 + x1) + (y0 + y1));
            g_K[((size_t)(b * TLEN + t0 + t)) * DMODEL + o] = s * 0.125f;
        }
    }
}

// ---------------------------------------------------------------------------
// Attention with softmax over HEADS (pointwise in (q,k)):
// Block: 256 threads, warp w == head h, lane == qi. Writes a partial-output
// slab for its k-split (no atomics).
// ---------------------------------------------------------------------------
extern __shared__ float smem[];

__global__ void __launch_bounds__(256, 1)
attn_kernel(const float* __restrict__ query,
            const float* __restrict__ value) {
    float* Ksh = smem;
    float* Vsh = smem + KSH_FLOATS;
    float* Psh = smem + KSH_FLOATS + VSH_FLOATS;

    const int tid = threadIdx.x;
    const int h   = tid >> 5;   // warp index == head
    const int qi  = tid & 31;   // lane == query within tile
    const int q0  = blockIdx.x * TQ;
    const int ks  = blockIdx.y;
    const int k0  = ks * KRANGE;
    const int b   = blockIdx.z;

    // q row for (h, qi) as 32 packed f32x2
    ull qreg2[32];
    {
        const float4* qp = (const float4*)(query + ((size_t)(b * TLEN + q0 + qi)) * DMODEL + h * DHEAD);
#pragma unroll
        for (int j = 0; j < 16; j++) {
            float4 t = qp[j];
            qreg2[2 * j + 0] = pk2(t.x, t.y);
            qreg2[2 * j + 1] = pk2(t.z, t.w);
        }
    }

    ull o2[32];
#pragma unroll
    for (int d = 0; d < 32; d++) o2[d] = 0ull;

    for (int kt = 0; kt < KRANGE; kt += TK) {
        __syncthreads();  // previous tile's phase C done before overwriting tiles

        // ---- load K tile (TK x DMODEL) and V tile (TK x DHEAD), coalesced ----
        {
            const float4* gk4 = (const float4*)(g_K + ((size_t)(b * TLEN + k0 + kt)) * DMODEL);
            float4* k4 = (float4*)Ksh;
            for (int i = tid; i < KSH_FLOATS / 4; i += 256) k4[i] = gk4[i];
            const float4* gv4 = (const float4*)(value + ((size_t)(b * TLEN + k0 + kt)) * DHEAD);
            float4* v4 = (float4*)Vsh;
            for (int i = tid; i < VSH_FLOATS / 4; i += 256) v4[i] = gv4[i];
        }
        __syncthreads();

        // ---- Phase A: logits S[h][ki][qi] = qreg . Ksh[ki][h*64:...] (f32x2) ----
#pragma unroll 2
        for (int ki = 0; ki < TK; ki++) {
            const float4* kp = (const float4*)(Ksh + ki * DMODEL + h * DHEAD);  // warp broadcast
            ull a0 = 0ull, a1 = 0ull, a2 = 0ull, a3 = 0ull;
#pragma unroll
            for (int j = 0; j < 16; j += 2) {
                float4 k0v = kp[j];
                float4 k1v = kp[j + 1];
                a0 = ffma2(qreg2[2 * j + 0], pk2(k0v.x, k0v.y), a0);
                a1 = ffma2(qreg2[2 * j + 1], pk2(k0v.z, k0v.w), a1);
                a2 = ffma2(qreg2[2 * j + 2], pk2(k1v.x, k1v.y), a2);
                a3 = ffma2(qreg2[2 * j + 3], pk2(k1v.z, k1v.w), a3);
            }
            float x0, x1, y0, y1, z0, z1, w0, w1;
            upk2(a0, x0, x1); upk2(a1, y0, y1); upk2(a2, z0, z1); upk2(a3, w0, w1);
            Psh[h * (TK * TQ) + ki * TQ + qi] = ((x0 + x1) + (y0 + y1)) + ((z0 + z1) + (w0 + w1));
        }
        __syncthreads();

        // ---- Phase B: softmax over the 8 heads for each (ki, qi) pair ----
#pragma unroll
        for (int r = 0; r < (TQ * TK) / 256; r++) {
            const int pi  = r * 256 + tid;
            const int kki = pi >> 5;       // ki
            const int qqi = pi & 31;       // qi (lane-consecutive -> conflict-free)
            float l[NHEADS];
#pragma unroll
            for (int hh = 0; hh < NHEADS; hh++)
                l[hh] = Psh[hh * (TK * TQ) + kki * TQ + qqi];
            float m = l[0];
#pragma unroll
            for (int hh = 1; hh < NHEADS; hh++) m = fmaxf(m, l[hh]);
            float ssum = 0.f;
#pragma unroll
            for (int hh = 0; hh < NHEADS; hh++) { l[hh] = __expf(l[hh] - m); ssum += l[hh]; }
            const float inv = __fdividef(1.f, ssum);
#pragma unroll
            for (int hh = 0; hh < NHEADS; hh++)
                Psh[hh * (TK * TQ) + kki * TQ + qqi] = l[hh] * inv;
        }
        __syncthreads();

        // ---- Phase C: o2[.] += P[h][ki][qi] * Vsh[ki][.] (f32x2) ----
        for (int ki = 0; ki < TK; ki++) {
            const float p = Psh[h * (TK * TQ) + ki * TQ + qi];
            const ull pp = pk2(p, p);
            const float4* vp = (const float4*)(Vsh + ki * DHEAD);  // warp broadcast
#pragma unroll
            for (int j = 0; j < 16; j++) {
                float4 vv = vp[j];
                o2[2 * j + 0] = ffma2(pp, pk2(vv.x, vv.y), o2[2 * j + 0]);
                o2[2 * j + 1] = ffma2(pp, pk2(vv.z, vv.w), o2[2 * j + 1]);
            }
        }
    }

    // ---- write this split's partial rows (plain stores, no atomics) ----
    float* op = g_part + (size_t)ks * OUT_FLOATS
              + ((size_t)(b * TLEN + q0 + qi)) * DMODEL + h * DHEAD;
#pragma unroll
    for (int j = 0; j < 16; j++) {
        float x0, x1, y0, y1;
        upk2(o2[2 * j + 0], x0, x1);
        upk2(o2[2 * j + 1], y0, y1);
        ((float4*)op)[j] = make_float4(x0, x1, y0, y1);
    }
}

// ---------------------------------------------------------------------------
// Final reduce over the KSPLIT partial slabs -> d_out
// grid 2048 x 256, float4 each
// ---------------------------------------------------------------------------
__global__ void reduce_kernel(float4* __restrict__ out) {
    const size_t i = (size_t)blockIdx.x * blockDim.x + threadIdx.x;  // float4 index
    const float4* p = (const float4*)g_part;
    const size_t slab = OUT_FLOATS / 4;
    float4 a = p[i];
#pragma unroll
    for (int s = 1; s < KSPLIT; s++) {
        float4 q = p[(size_t)s * slab + i];
        a.x += q.x; a.y += q.y; a.z += q.z; a.w += q.w;
    }
    out[i] = a;
}

// ---------------------------------------------------------------------------
extern "C" void kernel_launch(void* const* d_in, const int* in_sizes, int n_in,
                              void* d_out, int out_size) {
    const float* query = (const float*)d_in[0];   // [2,2048,512]
    const float* value = (const float*)d_in[1];   // [2,2048,64]
    const float* convw = (const float*)d_in[2];   // [512,64,1]
    const float* convb = (const float*)d_in[3];   // [512]
    float* out = (float*)d_out;                   // [2,2048,512]

    cudaFuncSetAttribute(attn_kernel, cudaFuncAttributeMaxDynamicSharedMemorySize, SMEM_BYTES);

    conv_kernel<<<dim3(TLEN / 16, BATCH), 256>>>(value, convw, convb);
    attn_kernel<<<dim3(TLEN / TQ, KSPLIT, BATCH), 256, SMEM_BYTES>>>(query, value);
    reduce_kernel<<<(OUT_FLOATS / 4) / 256, 256>>>((float4*)out);
}